// round 9
// baseline (speedup 1.0000x reference)
#include <cuda_runtime.h>
#include <cuda_bf16.h>

// ConeProjection: out[b,k] = P[k]^T * sigma[b] * P[k]
//   sigma[a][c] = (vn·w_a)(vn·w_c) - alpha*(w_a·w_c)
//   w0 = R[:,0], w1 = R[:,1], w2 = t - eyes, vn = v/max(||v||,1e-14)
//   P[k] = ((ki-6)/6, (kj-6)/6, 1),  k = 13*ki + kj
//
// One warp owns NB=32 batches; EVERY lane builds the 6 quadratic coefficients
// for its own batch (phase A, full lane utilization) into smem. Phase B loops
// the 32 batches: 2 broadcast LDS.128 + 6 coalesced store passes (k=lane+32p),
// 5 FFMA each, streaming stores. 64-thread blocks -> 2048 blocks, all
// co-resident in ONE balanced wave (fixes the R7 2-wave quantization).

#define K_GRID  169
#define NB      32            // batches per warp (= lanes)
#define WARPS   2             // warps per block
#define THREADS (WARPS * 32)

__global__ __launch_bounds__(THREADS)
void cone_projection_kernel(const float* __restrict__ eyes,
                            const float* __restrict__ v,
                            const float* __restrict__ R,
                            const float* __restrict__ t,
                            const float* __restrict__ alpha,
                            float* __restrict__ out,
                            int B)
{
    __shared__ float4 scoef[WARPS * NB * 2];  // per batch: (c0,c1,c2,c3),(c4,c5,-,-)

    const int lane = threadIdx.x & 31;
    const int wid  = threadIdx.x >> 5;
    const long long base_b = ((long long)blockIdx.x * WARPS + wid) * NB;

    // --- Per-thread grid coords for k = lane + 32p, p = 0..5 (12 registers) ---
    float xs[6], ys[6];
    #pragma unroll
    for (int p = 0; p < 6; ++p) {
        const int k  = lane + 32 * p;
        const int ki = (k * 79) >> 10;          // k/13, exact for k < 169
        const int kj = k - 13 * ki;
        xs[p] = (float)(ki - 6) * (1.0f / 6.0f);
        ys[p] = (float)(kj - 6) * (1.0f / 6.0f);
    }

    // --- Phase A: every lane builds coefficients for its own batch ---
    {
        const long long b = base_b + lane;
        if (b < B) {
            float vx = v[b * 3 + 0];
            float vy = v[b * 3 + 1];
            float vz = v[b * 3 + 2];
            float n  = fmaxf(sqrtf(vx * vx + vy * vy + vz * vz), 1e-14f);
            float inv = 1.0f / n;
            vx *= inv; vy *= inv; vz *= inv;

            const float a = alpha[b];

            const float* Rb = R + b * 9;
            const float w0x = Rb[0], w0y = Rb[3], w0z = Rb[6];   // R[:,0]
            const float w1x = Rb[1], w1y = Rb[4], w1z = Rb[7];   // R[:,1]
            const float w2x = t[b * 3 + 0] - eyes[b * 3 + 0];
            const float w2y = t[b * 3 + 1] - eyes[b * 3 + 1];
            const float w2z = t[b * 3 + 2] - eyes[b * 3 + 2];

            const float d0 = vx * w0x + vy * w0y + vz * w0z;
            const float d1 = vx * w1x + vy * w1y + vz * w1z;
            const float d2 = vx * w2x + vy * w2y + vz * w2z;

            const float c0 = d0 * d0 - a * (w0x * w0x + w0y * w0y + w0z * w0z); // x^2
            const float c1 = d1 * d1 - a * (w1x * w1x + w1y * w1y + w1z * w1z); // y^2
            const float c2 = d2 * d2 - a * (w2x * w2x + w2y * w2y + w2z * w2z); // 1
            const float c3 = 2.0f * (d0 * d1 - a * (w0x * w1x + w0y * w1y + w0z * w1z)); // xy
            const float c4 = 2.0f * (d0 * d2 - a * (w0x * w2x + w0y * w2y + w0z * w2z)); // x
            const float c5 = 2.0f * (d1 * d2 - a * (w1x * w2x + w1y * w2y + w1z * w2z)); // y

            const int s = (wid * NB + lane) * 2;
            scoef[s]     = make_float4(c0, c1, c2, c3);
            scoef[s + 1] = make_float4(c4, c5, 0.0f, 0.0f);
        }
    }
    __syncwarp();

    // --- Phase B: 32 batches x (2 broadcast LDS.128 + 6 x (5 FFMA + STG)) ---
    #pragma unroll 4
    for (int bt = 0; bt < NB; ++bt) {
        const long long b = base_b + bt;
        if (b >= B) break;

        const int s = (wid * NB + bt) * 2;
        const float4 ca = scoef[s];       // c0 c1 c2 c3
        const float4 cb = scoef[s + 1];   // c4 c5 -  -

        float* o = out + b * (long long)K_GRID + lane;

        #pragma unroll
        for (int p = 0; p < 6; ++p) {
            const float x = xs[p];
            const float y = ys[p];
            // r = x*(c0*x + c4) + y*(c1*y + c3*x + c5) + c2   (5 FFMA)
            const float t1 = fmaf(ca.x, x, cb.x);
            float       t2 = fmaf(ca.y, y, cb.y);
            t2 = fmaf(ca.w, x, t2);
            float r  = fmaf(x, t1, ca.z);
            r = fmaf(y, t2, r);
            if (p < 5 || lane < K_GRID - 160)   // last pass: k = 160+lane < 169
                __stcs(&o[p * 32], r);          // streaming (evict-first) store
        }
    }
}

extern "C" void kernel_launch(void* const* d_in, const int* in_sizes, int n_in,
                              void* d_out, int out_size) {
    const float* eyes  = (const float*)d_in[0];
    const float* v     = (const float*)d_in[1];
    const float* R     = (const float*)d_in[2];
    const float* t     = (const float*)d_in[3];
    const float* alpha = (const float*)d_in[4];
    float* out = (float*)d_out;

    const int B = in_sizes[4];                            // alpha: B elements
    const int warp_groups = (B + NB - 1) / NB;            // 4096 for B=131072
    const int blocks = (warp_groups + WARPS - 1) / WARPS; // 2048

    cone_projection_kernel<<<blocks, THREADS>>>(eyes, v, R, t, alpha, out, B);
}

// round 10
// speedup vs baseline: 1.4027x; 1.4027x over previous
#include <cuda_runtime.h>
#include <cuda_bf16.h>

// ConeProjection: out[b,k] = P[k]^T * sigma[b] * P[k]
//   sigma[a][c] = (vn·w_a)(vn·w_c) - alpha*(w_a·w_c)
//   w0 = R[:,0], w1 = R[:,1], w2 = t - eyes, vn = v/max(||v||,1e-14)
//   P[k] = ((ki-6)/6, (kj-6)/6, 1),  k = 13*ki + kj
//
// R7 structure (proven fastest inner loop) + single-wave residency:
// 256-thread blocks, grid=1024, __launch_bounds__(256,7) caps regs at 36 so
// 7 blocks/SM are resident -> all 1024 blocks in ONE wave (R7 ran 888+136,
// wasting ~40% of wall time on a nearly-empty second wave).
// Warp owns NB=16 batches: lanes 0..15 build quadratic coefficients into
// smem (__syncwarp only); phase B: per batch 2 broadcast LDS.128 + 6
// coalesced streaming-store passes (k = lane+32p), 5 FFMA each.

#define K_GRID  169
#define NB      16            // batches per warp
#define WARPS   8             // warps per block
#define THREADS (WARPS * 32)

__global__ __launch_bounds__(THREADS, 7)
void cone_projection_kernel(const float* __restrict__ eyes,
                            const float* __restrict__ v,
                            const float* __restrict__ R,
                            const float* __restrict__ t,
                            const float* __restrict__ alpha,
                            float* __restrict__ out,
                            int B)
{
    __shared__ float4 scoef[WARPS * NB * 2];   // per batch: (c0,c1,c2,c3),(c4,c5,-,-)

    const int lane = threadIdx.x & 31;
    const int wid  = threadIdx.x >> 5;
    const long long base_b = ((long long)blockIdx.x * WARPS + wid) * NB;

    // --- Per-thread grid coords for k = lane + 32p, p = 0..5 (12 registers) ---
    float xs[6], ys[6];
    #pragma unroll
    for (int p = 0; p < 6; ++p) {
        const int k  = lane + 32 * p;
        const int ki = (k * 79) >> 10;          // k/13, exact for k < 169
        const int kj = k - 13 * ki;
        xs[p] = (float)(ki - 6) * (1.0f / 6.0f);
        ys[p] = (float)(kj - 6) * (1.0f / 6.0f);
    }

    // --- Phase A: lanes 0..15 build coefficients for their batch ---
    if (lane < NB) {
        const long long b = base_b + lane;
        if (b < B) {
            float vx = v[b * 3 + 0];
            float vy = v[b * 3 + 1];
            float vz = v[b * 3 + 2];
            float n  = fmaxf(sqrtf(vx * vx + vy * vy + vz * vz), 1e-14f);
            float inv = 1.0f / n;
            vx *= inv; vy *= inv; vz *= inv;

            const float a = alpha[b];

            const float* Rb = R + b * 9;
            const float w0x = Rb[0], w0y = Rb[3], w0z = Rb[6];   // R[:,0]
            const float w1x = Rb[1], w1y = Rb[4], w1z = Rb[7];   // R[:,1]
            const float w2x = t[b * 3 + 0] - eyes[b * 3 + 0];
            const float w2y = t[b * 3 + 1] - eyes[b * 3 + 1];
            const float w2z = t[b * 3 + 2] - eyes[b * 3 + 2];

            const float d0 = vx * w0x + vy * w0y + vz * w0z;
            const float d1 = vx * w1x + vy * w1y + vz * w1z;
            const float d2 = vx * w2x + vy * w2y + vz * w2z;

            const float c0 = d0 * d0 - a * (w0x * w0x + w0y * w0y + w0z * w0z); // x^2
            const float c1 = d1 * d1 - a * (w1x * w1x + w1y * w1y + w1z * w1z); // y^2
            const float c2 = d2 * d2 - a * (w2x * w2x + w2y * w2y + w2z * w2z); // 1
            const float c3 = 2.0f * (d0 * d1 - a * (w0x * w1x + w0y * w1y + w0z * w1z)); // xy
            const float c4 = 2.0f * (d0 * d2 - a * (w0x * w2x + w0y * w2y + w0z * w2z)); // x
            const float c5 = 2.0f * (d1 * d2 - a * (w1x * w2x + w1y * w2y + w1z * w2z)); // y

            const int s = (wid * NB + lane) * 2;
            scoef[s]     = make_float4(c0, c1, c2, c3);
            scoef[s + 1] = make_float4(c4, c5, 0.0f, 0.0f);
        }
    }
    __syncwarp();

    // --- Phase B: 16 batches x (2 broadcast LDS.128 + 6 x (5 FFMA + STG)) ---
    #pragma unroll 4
    for (int bt = 0; bt < NB; ++bt) {
        const long long b = base_b + bt;
        if (b >= B) break;

        const int s = (wid * NB + bt) * 2;
        const float4 ca = scoef[s];       // c0 c1 c2 c3
        const float4 cb = scoef[s + 1];   // c4 c5 -  -

        float* o = out + b * (long long)K_GRID + lane;

        #pragma unroll
        for (int p = 0; p < 6; ++p) {
            const float x = xs[p];
            const float y = ys[p];
            // r = x*(c0*x + c4) + y*(c1*y + c3*x + c5) + c2   (5 FFMA)
            const float t1 = fmaf(ca.x, x, cb.x);
            float       t2 = fmaf(ca.y, y, cb.y);
            t2 = fmaf(ca.w, x, t2);
            float r  = fmaf(x, t1, ca.z);
            r = fmaf(y, t2, r);
            if (p < 5 || lane < K_GRID - 160)   // last pass: k = 160+lane < 169
                __stcs(&o[p * 32], r);          // streaming (evict-first) store
        }
    }
}

extern "C" void kernel_launch(void* const* d_in, const int* in_sizes, int n_in,
                              void* d_out, int out_size) {
    const float* eyes  = (const float*)d_in[0];
    const float* v     = (const float*)d_in[1];
    const float* R     = (const float*)d_in[2];
    const float* t     = (const float*)d_in[3];
    const float* alpha = (const float*)d_in[4];
    float* out = (float*)d_out;

    const int B = in_sizes[4];                            // alpha: B elements
    const int warp_groups = (B + NB - 1) / NB;            // 8192 for B=131072
    const int blocks = (warp_groups + WARPS - 1) / WARPS; // 1024

    cone_projection_kernel<<<blocks, THREADS>>>(eyes, v, R, t, alpha, out, B);
}